// round 12
// baseline (speedup 1.0000x reference)
#include <cuda_runtime.h>
#include <cuda_bf16.h>
#include <cstdint>
#include <math.h>

// ---------------------------------------------------------------------------
// Problem constants
// ---------------------------------------------------------------------------
#define NN       262144
#define NE       2097152
#define F_IN     64
#define C1       128
#define C2       96
#define BATCH    4096
#define NODES    64
#define IN_MLP   6144
#define HID      2048
#define HID4     512
#define OUTF     256
#define NEG_SLOPE 0.01f
#define EPS      1e-5f

typedef __nv_bfloat16 bf16;

// ---------------------------------------------------------------------------
// Scratch
// ---------------------------------------------------------------------------
__device__ int   g_hist_src[NN];
__device__ int   g_hist_dst[NN];
__device__ int   g_part    [NN];
__device__ int   g_bsum    [NN / 256];
__device__ int   g_off     [NN + 1];
__device__ int   g_cursor  [NN];
__device__ int2  g_edge    [NE];          // (src, ew*rs_out[src]) sorted by dst
__device__ float g_rs_out  [NN];
__device__ float g_rs_in   [NN];
__device__ float g_h2      [(size_t)NN * C2];
__device__ float g_m1      [(size_t)BATCH * HID];
__device__ float g_m2      [(size_t)BATCH * HID4];
// bf16 hi/lo split planes
__device__ bf16 g_agg1_hi[(size_t)NN * F_IN];
__device__ bf16 g_agg1_lo[(size_t)NN * F_IN];
__device__ bf16 g_g1_hi  [(size_t)NN * C1];
__device__ bf16 g_g1_lo  [(size_t)NN * C1];
__device__ bf16 g_gn2_hi [(size_t)NN * C2];
__device__ bf16 g_gn2_lo [(size_t)NN * C2];
__device__ bf16 g_m1_hi  [(size_t)BATCH * HID];
__device__ bf16 g_m1_lo  [(size_t)BATCH * HID];
__device__ bf16 g_m2_hi  [(size_t)BATCH * HID4];
__device__ bf16 g_m2_lo  [(size_t)BATCH * HID4];
// transposed split weights
__device__ bf16 g_W1T_hi [C1 * F_IN];
__device__ bf16 g_W1T_lo [C1 * F_IN];
__device__ bf16 g_W2T_hi [128 * C1];
__device__ bf16 g_W2T_lo [128 * C1];
__device__ bf16 g_WinT_hi[(size_t)HID * IN_MLP];
__device__ bf16 g_WinT_lo[(size_t)HID * IN_MLP];
__device__ bf16 g_WhT_hi [(size_t)HID4 * HID];
__device__ bf16 g_WhT_lo [(size_t)HID4 * HID];
__device__ bf16 g_WcT_hi [OUTF * HID4];
__device__ bf16 g_WcT_lo [OUTF * HID4];

// ---------------------------------------------------------------------------
// Helpers
// ---------------------------------------------------------------------------
__device__ __forceinline__ void cp_async16(uint32_t dst, const void* src) {
    asm volatile("cp.async.cg.shared.global [%0], [%1], 16;" :: "r"(dst), "l"(src));
}

__device__ __forceinline__ uint32_t smem_u32(const void* p) {
    uint32_t r;
    asm("{ .reg .u64 t; cvta.to.shared.u64 t, %1; cvt.u32.u64 %0, t; }"
        : "=r"(r) : "l"(p));
    return r;
}

__device__ __forceinline__ void mma_bf16(float (&d)[4], const uint32_t (&a)[4],
                                         const uint32_t (&b)[2]) {
    asm volatile(
        "mma.sync.aligned.m16n8k16.row.col.f32.bf16.bf16.f32 "
        "{%0,%1,%2,%3}, {%4,%5,%6,%7}, {%8,%9}, {%0,%1,%2,%3};"
        : "+f"(d[0]), "+f"(d[1]), "+f"(d[2]), "+f"(d[3])
        : "r"(a[0]), "r"(a[1]), "r"(a[2]), "r"(a[3]), "r"(b[0]), "r"(b[1]));
}

__device__ __forceinline__ void ldsm_x4(uint32_t (&r)[4], uint32_t addr) {
    asm volatile("ldmatrix.sync.aligned.m8n8.x4.shared.b16 {%0,%1,%2,%3}, [%4];"
                 : "=r"(r[0]), "=r"(r[1]), "=r"(r[2]), "=r"(r[3]) : "r"(addr));
}

__device__ __forceinline__ void split_bf16(float v, bf16& h, bf16& l) {
    h = __float2bfloat16(v);
    l = __float2bfloat16(v - __bfloat162float(h));
}

__device__ __forceinline__ float leaky(float v) {
    return (v >= 0.0f) ? v : NEG_SLOPE * v;
}

// ---------------------------------------------------------------------------
// CSR build
// ---------------------------------------------------------------------------
__global__ void zero_hist_kernel(int* __restrict__ a, int* __restrict__ b, int n) {
    int i = blockIdx.x * blockDim.x + threadIdx.x;
    if (i < n) { a[i] = 0; b[i] = 0; }
}

__global__ void hist_kernel(const int* __restrict__ src, const int* __restrict__ dst,
                            int E, int* __restrict__ hs, int* __restrict__ hd) {
    int i = blockIdx.x * blockDim.x + threadIdx.x;
    if (i < E) {
        atomicAdd(&hs[src[i]], 1);
        atomicAdd(&hd[dst[i]], 1);
    }
}

__global__ void scanA_kernel(const int* __restrict__ h, int* __restrict__ part,
                             int* __restrict__ bsum, int n) {
    __shared__ int wsum[8];
    int i = blockIdx.x * 256 + threadIdx.x;
    int t = threadIdx.x, lane = t & 31, w = t >> 5;
    int v = (i < n) ? h[i] : 0;
    int inc = v;
#pragma unroll
    for (int o = 1; o < 32; o <<= 1) {
        int u = __shfl_up_sync(0xffffffffu, inc, o);
        if (lane >= o) inc += u;
    }
    if (lane == 31) wsum[w] = inc;
    __syncthreads();
    if (w == 0) {
        int s = (lane < 8) ? wsum[lane] : 0;
#pragma unroll
        for (int o = 1; o < 8; o <<= 1) {
            int u = __shfl_up_sync(0xffffffffu, s, o);
            if (lane >= o) s += u;
        }
        if (lane < 8) wsum[lane] = s;
    }
    __syncthreads();
    int base = (w > 0) ? wsum[w - 1] : 0;
    if (i < n) part[i] = base + inc - v;
    if (t == 255) bsum[blockIdx.x] = base + inc;
}

__global__ void scanB_kernel(int* __restrict__ bsum, int nb) {
    __shared__ int wsum[32];
    int t = threadIdx.x, lane = t & 31, w = t >> 5;
    int v = (t < nb) ? bsum[t] : 0;
    int inc = v;
#pragma unroll
    for (int o = 1; o < 32; o <<= 1) {
        int u = __shfl_up_sync(0xffffffffu, inc, o);
        if (lane >= o) inc += u;
    }
    if (lane == 31) wsum[w] = inc;
    __syncthreads();
    if (w == 0) {
        int s = wsum[lane];
#pragma unroll
        for (int o = 1; o < 32; o <<= 1) {
            int u = __shfl_up_sync(0xffffffffu, s, o);
            if (lane >= o) s += u;
        }
        wsum[lane] = s;
    }
    __syncthreads();
    int base = (w > 0) ? wsum[w - 1] : 0;
    if (t < nb) bsum[t] = base + inc - v;
}

// scanC: offsets + cursors, and fused rsqrt-degree computation.
__global__ void scanC_kernel(const int* __restrict__ part, const int* __restrict__ bsum,
                             int* __restrict__ off, int* __restrict__ cursor,
                             const int* __restrict__ hs, const int* __restrict__ hd,
                             float* __restrict__ rso, float* __restrict__ rsi,
                             int n, int E) {
    int i = blockIdx.x * blockDim.x + threadIdx.x;
    if (i < n) {
        int o = part[i] + bsum[i >> 8];
        off[i] = o;
        cursor[i] = o;
        rso[i] = rsqrtf(fmaxf((float)hs[i], 1.0f));
        rsi[i] = rsqrtf(fmaxf((float)hd[i], 1.0f));
    }
    if (i == 0) off[n] = E;
}

// fill: pack (src, ew*rs_out[src]) per edge into dst-sorted order.
__global__ void fill_kernel(const int* __restrict__ dst, const int* __restrict__ src,
                            const float* __restrict__ ew, const float* __restrict__ rs_out,
                            int E, int* __restrict__ cursor, int2* __restrict__ edge) {
    int i = blockIdx.x * blockDim.x + threadIdx.x;
    if (i < E) {
        int s = src[i];
        float w = ew[i] * rs_out[s];
        int p = atomicAdd(&cursor[dst[i]], 1);
        edge[p] = make_int2(s, __float_as_int(w));
    }
}

// ---------------------------------------------------------------------------
// gather1: agg1[d] = sum_e x[src] * w_packed; bf16 planes out. Warp/node.
// Unroll-4 edge loop: 8 independent loads in flight per warp.
// ---------------------------------------------------------------------------
__global__ void gather1_kernel(const float* __restrict__ x, const int2* __restrict__ edge,
                               const int* __restrict__ off,
                               bf16* __restrict__ hi, bf16* __restrict__ lo, int n) {
    int d = blockIdx.x * 8 + (threadIdx.x >> 5);
    if (d >= n) return;
    int lane = threadIdx.x & 31;
    int j0 = off[d], j1 = off[d + 1];
    float2 acc = make_float2(0.0f, 0.0f);
    int j = j0;
    for (; j + 3 < j1; j += 4) {
        int2 e0 = edge[j], e1 = edge[j + 1], e2 = edge[j + 2], e3 = edge[j + 3];
        float2 v0 = reinterpret_cast<const float2*>(x)[(size_t)e0.x * 32 + lane];
        float2 v1 = reinterpret_cast<const float2*>(x)[(size_t)e1.x * 32 + lane];
        float2 v2 = reinterpret_cast<const float2*>(x)[(size_t)e2.x * 32 + lane];
        float2 v3 = reinterpret_cast<const float2*>(x)[(size_t)e3.x * 32 + lane];
        float w0 = __int_as_float(e0.y), w1 = __int_as_float(e1.y);
        float w2 = __int_as_float(e2.y), w3 = __int_as_float(e3.y);
        acc.x = fmaf(v0.x, w0, acc.x); acc.y = fmaf(v0.y, w0, acc.y);
        acc.x = fmaf(v1.x, w1, acc.x); acc.y = fmaf(v1.y, w1, acc.y);
        acc.x = fmaf(v2.x, w2, acc.x); acc.y = fmaf(v2.y, w2, acc.y);
        acc.x = fmaf(v3.x, w3, acc.x); acc.y = fmaf(v3.y, w3, acc.y);
    }
    for (; j < j1; j++) {
        int2 e = edge[j];
        float w = __int_as_float(e.y);
        float2 v = reinterpret_cast<const float2*>(x)[(size_t)e.x * 32 + lane];
        acc.x = fmaf(v.x, w, acc.x);
        acc.y = fmaf(v.y, w, acc.y);
    }
    bf16 h0, l0, h1, l1;
    split_bf16(acc.x, h0, l0);
    split_bf16(acc.y, h1, l1);
    reinterpret_cast<__nv_bfloat162*>(hi)[(size_t)d * 32 + lane] = __nv_bfloat162(h0, h1);
    reinterpret_cast<__nv_bfloat162*>(lo)[(size_t)d * 32 + lane] = __nv_bfloat162(l0, l1);
}

// ---------------------------------------------------------------------------
// Fused gather2 + graphnorm2: one block per graph (64 nodes x 96 feats).
// Unroll-4 edge loop: 12 feature-row loads in flight per warp.
// ---------------------------------------------------------------------------
__global__ __launch_bounds__(256)
void gather2_gn_kernel(const float* __restrict__ h2, const int2* __restrict__ edge,
                       const int* __restrict__ off, const float* __restrict__ rs_in,
                       const float* __restrict__ alpha, const float* __restrict__ gamma,
                       const float* __restrict__ beta,
                       bf16* __restrict__ hi, bf16* __restrict__ lo) {
    __shared__ float sm[NODES * C2];
    __shared__ float s_scale[C2], s_bias[C2];
    int g = blockIdx.x;
    int wid = threadIdx.x >> 5, lane = threadIdx.x & 31;

    // phase 1: gather + rs_in + leaky into smem
    for (int nl = wid; nl < NODES; nl += 8) {
        int d = g * NODES + nl;
        int j0 = off[d], j1 = off[d + 1];
        float a0 = 0.0f, a1 = 0.0f, a2 = 0.0f;
        int j = j0;
        for (; j + 3 < j1; j += 4) {
            int2 e0 = edge[j], e1 = edge[j + 1], e2 = edge[j + 2], e3 = edge[j + 3];
            const float* p0 = h2 + (size_t)e0.x * 96;
            const float* p1 = h2 + (size_t)e1.x * 96;
            const float* p2 = h2 + (size_t)e2.x * 96;
            const float* p3 = h2 + (size_t)e3.x * 96;
            float x00 = p0[lane], x01 = p0[lane + 32], x02 = p0[lane + 64];
            float x10 = p1[lane], x11 = p1[lane + 32], x12 = p1[lane + 64];
            float x20 = p2[lane], x21 = p2[lane + 32], x22 = p2[lane + 64];
            float x30 = p3[lane], x31 = p3[lane + 32], x32 = p3[lane + 64];
            float w0 = __int_as_float(e0.y), w1 = __int_as_float(e1.y);
            float w2 = __int_as_float(e2.y), w3 = __int_as_float(e3.y);
            a0 = fmaf(x00, w0, a0); a1 = fmaf(x01, w0, a1); a2 = fmaf(x02, w0, a2);
            a0 = fmaf(x10, w1, a0); a1 = fmaf(x11, w1, a1); a2 = fmaf(x12, w1, a2);
            a0 = fmaf(x20, w2, a0); a1 = fmaf(x21, w2, a1); a2 = fmaf(x22, w2, a2);
            a0 = fmaf(x30, w3, a0); a1 = fmaf(x31, w3, a1); a2 = fmaf(x32, w3, a2);
        }
        for (; j < j1; j++) {
            int2 e = edge[j];
            float w = __int_as_float(e.y);
            const float* hp = h2 + (size_t)e.x * 96;
            a0 = fmaf(hp[lane], w, a0);
            a1 = fmaf(hp[lane + 32], w, a1);
            a2 = fmaf(hp[lane + 64], w, a2);
        }
        float ri = rs_in[d];
        sm[nl * 96 + lane]      = leaky(a0 * ri);
        sm[nl * 96 + lane + 32] = leaky(a1 * ri);
        sm[nl * 96 + lane + 64] = leaky(a2 * ri);
    }
    __syncthreads();

    // phase 2: per-channel stats -> folded scale/bias
    int c = threadIdx.x;
    if (c < C2) {
        float sum = 0.0f;
#pragma unroll 8
        for (int r = 0; r < NODES; r++) sum += sm[r * C2 + c];
        float mean = sum * (1.0f / NODES);
        float am = alpha[c] * mean;
        float var = 0.0f;
#pragma unroll 8
        for (int r = 0; r < NODES; r++) {
            float s = sm[r * C2 + c] - am;
            var += s * s;
        }
        var *= (1.0f / NODES);
        float inv = rsqrtf(var + EPS);
        float gmm = gamma[c];
        s_scale[c] = gmm * inv;
        s_bias[c]  = beta[c] - gmm * am * inv;
    }
    __syncthreads();

    // phase 3: coalesced row-major emission
    size_t obase = (size_t)g * NODES * C2;
    __nv_bfloat162* h2p = reinterpret_cast<__nv_bfloat162*>(hi + obase);
    __nv_bfloat162* l2p = reinterpret_cast<__nv_bfloat162*>(lo + obase);
    for (int idx = threadIdx.x; idx < (NODES * C2) / 2; idx += 256) {
        int e0 = idx * 2;
        int c0 = e0 % C2;
        float v0 = fmaf(sm[e0],     s_scale[c0],     s_bias[c0]);
        float v1 = fmaf(sm[e0 + 1], s_scale[c0 + 1], s_bias[c0 + 1]);
        bf16 h0, l0, h1, l1;
        split_bf16(v0, h0, l0);
        split_bf16(v1, h1, l1);
        h2p[idx] = __nv_bfloat162(h0, h1);
        l2p[idx] = __nv_bfloat162(l0, l1);
    }
}

// ---------------------------------------------------------------------------
// Transpose in[R,C] -> hi/lo[C,R] bf16 split planes.
// ---------------------------------------------------------------------------
__global__ void transpose_split_kernel(const float* __restrict__ in,
                                       bf16* __restrict__ hi, bf16* __restrict__ lo,
                                       int R, int C) {
    __shared__ float t[32][33];
    int c0 = blockIdx.x * 32, r0 = blockIdx.y * 32;
    int x = threadIdx.x, y = threadIdx.y;
#pragma unroll
    for (int dy = 0; dy < 32; dy += 8) {
        int r = r0 + y + dy, c = c0 + x;
        t[y + dy][x] = (r < R && c < C) ? in[(size_t)r * C + c] : 0.0f;
    }
    __syncthreads();
#pragma unroll
    for (int dy = 0; dy < 32; dy += 8) {
        int oc = c0 + y + dy, orr = r0 + x;
        if (oc < C && orr < R) {
            bf16 h, l;
            split_bf16(t[x][y + dy], h, l);
            hi[(size_t)oc * R + orr] = h;
            lo[(size_t)oc * R + orr] = l;
        }
    }
}

// ---------------------------------------------------------------------------
// bf16x3 mma.sync GEMM core -- fragment loads via ldmatrix.x4
// ---------------------------------------------------------------------------
#define GBM 256
#define GBN 128
#define GBK 32
#define ROWB 80
#define A_PLANE (GBM * ROWB)
#define B_PLANE (GBN * ROWB)
#define OFF_AHI 0
#define OFF_ALO (A_PLANE)
#define OFF_BHI (2 * A_PLANE)
#define OFF_BLO (2 * A_PLANE + B_PLANE)
#define STAGE_B (2 * A_PLANE + 2 * B_PLANE)
#define GEMM_SMEM (3 * STAGE_B)

__device__ __forceinline__ void gemm_load_stage(const bf16* __restrict__ Ahi,
                                                const bf16* __restrict__ Alo,
                                                const bf16* __restrict__ Bhi,
                                                const bf16* __restrict__ Blo,
                                                int K, int m0, int n0, int k0,
                                                uint32_t sbuf, int tid) {
#pragma unroll
    for (int p = 0; p < 4; p++) {
        int id = tid + (p << 8);
        int r = id >> 2, c = id & 3;
        size_t g = (size_t)(m0 + r) * K + k0 + c * 8;
        uint32_t o = r * ROWB + c * 16;
        cp_async16(sbuf + OFF_AHI + o, Ahi + g);
        cp_async16(sbuf + OFF_ALO + o, Alo + g);
    }
#pragma unroll
    for (int p = 0; p < 2; p++) {
        int id = tid + (p << 8);
        int r = id >> 2, c = id & 3;
        size_t g = (size_t)(n0 + r) * K + k0 + c * 8;
        uint32_t o = r * ROWB + c * 16;
        cp_async16(sbuf + OFF_BHI + o, Bhi + g);
        cp_async16(sbuf + OFF_BLO + o, Blo + g);
    }
}

// Mainloop producing acc[4][8][4]; expects sbase, tid, wid, lane, warp_m,
// warp_n, m0, n0, K, T in scope. Fragment loads via ldmatrix (conflict-free
// on the 80B row stride).
#define GEMM_MAINLOOP(Ahi, Alo, Bhi, Blo)                                        \
    _Pragma("unroll")                                                            \
    for (int s = 0; s < 2; s++) {                                                \
        if (s < T) gemm_load_stage(Ahi, Alo, Bhi, Blo, K, m0, n0, s * GBK,       \
                                   sbase + s * STAGE_B, tid);                    \
        asm volatile("cp.async.commit_group;" ::: "memory");                     \
    }                                                                            \
    {                                                                            \
        const int a_row  = (lane & 7) + ((lane >> 3) & 1) * 8;                   \
        const uint32_t a_koff = ((uint32_t)(lane >> 4)) * 16;                    \
        const int b_row  = (lane & 7) + ((lane >> 4) & 1) * 8;                   \
        const uint32_t b_koff = ((uint32_t)((lane >> 3) & 1)) * 16;              \
        for (int i = 0; i < T; i++) {                                            \
            if (i + 1 < T) asm volatile("cp.async.wait_group 1;" ::: "memory");  \
            else           asm volatile("cp.async.wait_group 0;" ::: "memory");  \
            __syncthreads();                                                     \
            if (i + 2 < T)                                                       \
                gemm_load_stage(Ahi, Alo, Bhi, Blo, K, m0, n0, (i + 2) * GBK,    \
                                sbase + ((i + 2) % 3) * STAGE_B, tid);           \
            asm volatile("cp.async.commit_group;" ::: "memory");                 \
            const uint32_t sbu = sbase + (i % 3) * STAGE_B;                      \
            _Pragma("unroll")                                                    \
            for (int ks = 0; ks < 2; ks++) {                                     \
                const uint32_t kbase = (uint32_t)(ks * 32);                      \
                uint32_t ahi[4][4], alo[4][4];                                   \
                _Pragma("unroll")                                                \
                for (int mt = 0; mt < 4; mt++) {                                 \
                    uint32_t ar = (uint32_t)(warp_m * 64 + mt * 16 + a_row);     \
                    uint32_t aaddr = sbu + OFF_AHI + ar * ROWB + kbase + a_koff; \
                    ldsm_x4(ahi[mt], aaddr);                                     \
                    ldsm_x4(alo[mt], aaddr + (OFF_ALO - OFF_AHI));               \
                }                                                                \
                uint32_t bhi[8][2], blo[8][2];                                   \
                _Pragma("unroll")                                                \
                for (int p = 0; p < 4; p++) {                                    \
                    uint32_t br = (uint32_t)(warp_n * 64 + p * 16 + b_row);      \
                    uint32_t baddr = sbu + OFF_BHI + br * ROWB + kbase + b_koff; \
                    uint32_t th[4], tl[4];                                       \
                    ldsm_x4(th, baddr);                                          \
                    ldsm_x4(tl, baddr + (OFF_BLO - OFF_BHI));                    \
                    bhi[p * 2][0] = th[0]; bhi[p * 2][1] = th[1];                \
                    bhi[p * 2 + 1][0] = th[2]; bhi[p * 2 + 1][1] = th[3];        \
                    blo[p * 2][0] = tl[0]; blo[p * 2][1] = tl[1];                \
                    blo[p * 2 + 1][0] = tl[2]; blo[p * 2 + 1][1] = tl[3];        \
                }                                                                \
                _Pragma("unroll")                                                \
                for (int mt = 0; mt < 4; mt++)                                   \
                    _Pragma("unroll")                                            \
                    for (int nt = 0; nt < 8; nt++) {                             \
                        float (&d)[4] = acc[mt][nt];                             \
                        mma_bf16(d, ahi[mt], bhi[nt]);                           \
                        mma_bf16(d, ahi[mt], blo[nt]);                           \
                        mma_bf16(d, alo[mt], bhi[nt]);                           \
                    }                                                            \
            }                                                                    \
        }                                                                        \
    }

// Generic GEMM: fp32 C output, optional rowscale + leaky.
__global__ __launch_bounds__(256, 1)
void bf16x3_gemm_kernel(int M, int K, int Nout,
                        const bf16* __restrict__ Ahi, const bf16* __restrict__ Alo,
                        const bf16* __restrict__ Bhi, const bf16* __restrict__ Blo,
                        float* __restrict__ C,
                        const float* __restrict__ rowscale, int do_leaky) {
    extern __shared__ char dynsm[];
    const uint32_t sbase = smem_u32(dynsm);
    const int tid = threadIdx.x, wid = tid >> 5, lane = tid & 31;
    const int warp_m = wid & 3, warp_n = wid >> 2;
    const int m0 = blockIdx.y * GBM, n0 = blockIdx.x * GBN;

    float acc[4][8][4];
#pragma unroll
    for (int mt = 0; mt < 4; mt++)
#pragma unroll
        for (int nt = 0; nt < 8; nt++)
#pragma unroll
            for (int j = 0; j < 4; j++) acc[mt][nt][j] = 0.0f;

    const int T = K / GBK;
    GEMM_MAINLOOP(Ahi, Alo, Bhi, Blo)

#pragma unroll
    for (int mt = 0; mt < 4; mt++) {
        const int r0 = m0 + warp_m * 64 + mt * 16 + (lane >> 2);
        const int r1 = r0 + 8;
        const float s0 = rowscale ? rowscale[r0] : 1.0f;
        const float s1 = rowscale ? rowscale[r1] : 1.0f;
#pragma unroll
        for (int nt = 0; nt < 8; nt++) {
            const int c = n0 + warp_n * 64 + nt * 8 + (lane & 3) * 2;
            if (c < Nout) {
                float v0 = acc[mt][nt][0] * s0;
                float v1 = acc[mt][nt][1] * s0;
                float v2 = acc[mt][nt][2] * s1;
                float v3 = acc[mt][nt][3] * s1;
                if (do_leaky) { v0 = leaky(v0); v1 = leaky(v1); v2 = leaky(v2); v3 = leaky(v3); }
                *reinterpret_cast<float2*>(C + (size_t)r0 * Nout + c) = make_float2(v0, v1);
                *reinterpret_cast<float2*>(C + (size_t)r1 * Nout + c) = make_float2(v2, v3);
            }
        }
    }
}

// GEMM1 + fused graphnorm1 (rs_out lives in the edge weights).
__global__ __launch_bounds__(256, 1)
void gemm1_gn_kernel(const bf16* __restrict__ Ahi, const bf16* __restrict__ Alo,
                     const bf16* __restrict__ Bhi, const bf16* __restrict__ Blo,
                     const float* __restrict__ rs_in,
                     const float* __restrict__ alpha, const float* __restrict__ gamma,
                     const float* __restrict__ beta,
                     bf16* __restrict__ hi, bf16* __restrict__ lo) {
    extern __shared__ char dynsm[];
    const uint32_t sbase = smem_u32(dynsm);
    const int tid = threadIdx.x, wid = tid >> 5, lane = tid & 31;
    const int warp_m = wid & 3, warp_n = wid >> 2;
    const int m0 = blockIdx.y * GBM, n0 = 0;
    const int K = F_IN;

    float acc[4][8][4];
#pragma unroll
    for (int mt = 0; mt < 4; mt++)
#pragma unroll
        for (int nt = 0; nt < 8; nt++)
#pragma unroll
            for (int j = 0; j < 4; j++) acc[mt][nt][j] = 0.0f;

    const int T = K / GBK;   // 2
    GEMM_MAINLOOP(Ahi, Alo, Bhi, Blo)

    // pre-op: v = leaky(acc * rs_in[row])
#pragma unroll
    for (int mt = 0; mt < 4; mt++) {
        const int gr0 = m0 + warp_m * 64 + mt * 16 + (lane >> 2);
        const float ri0 = rs_in[gr0], ri1 = rs_in[gr0 + 8];
#pragma unroll
        for (int nt = 0; nt < 8; nt++) {
            acc[mt][nt][0] = leaky(acc[mt][nt][0] * ri0);
            acc[mt][nt][1] = leaky(acc[mt][nt][1] * ri0);
            acc[mt][nt][2] = leaky(acc[mt][nt][2] * ri1);
            acc[mt][nt][3] = leaky(acc[mt][nt][3] * ri1);
        }
    }

    // column stats over this warp's 64 rows
    const int cbase = warp_n * 64 + (lane & 3) * 2;
    float am0[8], am1[8], inv0[8], inv1[8];
#pragma unroll
    for (int nt = 0; nt < 8; nt++) {
        float s0 = 0.0f, s1 = 0.0f;
#pragma unroll
        for (int mt = 0; mt < 4; mt++) {
            s0 += acc[mt][nt][0] + acc[mt][nt][2];
            s1 += acc[mt][nt][1] + acc[mt][nt][3];
        }
#pragma unroll
        for (int o = 4; o <= 16; o <<= 1) {
            s0 += __shfl_xor_sync(0xffffffffu, s0, o);
            s1 += __shfl_xor_sync(0xffffffffu, s1, o);
        }
        const int c = cbase + nt * 8;
        float2 al = *reinterpret_cast<const float2*>(alpha + c);
        am0[nt] = al.x * s0 * (1.0f / NODES);
        am1[nt] = al.y * s1 * (1.0f / NODES);

        float q0 = 0.0f, q1 = 0.0f;
#pragma unroll
        for (int mt = 0; mt < 4; mt++) {
            float d0 = acc[mt][nt][0] - am0[nt], d2 = acc[mt][nt][2] - am0[nt];
            float d1 = acc[mt][nt][1] - am1[nt], d3 = acc[mt][nt][3] - am1[nt];
            q0 += d0 * d0 + d2 * d2;
            q1 += d1 * d1 + d3 * d3;
        }
#pragma unroll
        for (int o = 4; o <= 16; o <<= 1) {
            q0 += __shfl_xor_sync(0xffffffffu, q0, o);
            q1 += __shfl_xor_sync(0xffffffffu, q1, o);
        }
        inv0[nt] = rsqrtf(q0 * (1.0f / NODES) + EPS);
        inv1[nt] = rsqrtf(q1 * (1.0f / NODES) + EPS);
    }

    // normalize, split, store planes
#pragma unroll
    for (int mt = 0; mt < 4; mt++) {
        const int gr0 = m0 + warp_m * 64 + mt * 16 + (lane >> 2);
        const int gr1 = gr0 + 8;
#pragma unroll
        for (int nt = 0; nt < 8; nt++) {
            const int c = cbase + nt * 8;
            float2 gm = *reinterpret_cast<const float2*>(gamma + c);
            float2 bt = *reinterpret_cast<const float2*>(beta + c);
            float o0 = gm.x * (acc[mt][nt][0] - am0[nt]) * inv0[nt] + bt.x;
            float o1 = gm.y * (acc[mt][nt][1] - am1[nt]) * inv1[nt] + bt.y;
            float o2 = gm.x * (acc[mt][nt][2] - am0[nt]) * inv0[nt] + bt.x;
            float o3 = gm.y * (acc[mt][nt][3] - am1[nt]) * inv1[nt] + bt.y;
            bf16 h0, l0, h1, l1, h2v, l2v, h3, l3;
            split_bf16(o0, h0, l0); split_bf16(o1, h1, l1);
            split_bf16(o2, h2v, l2v); split_bf16(o3, h3, l3);
            *reinterpret_cast<__nv_bfloat162*>(hi + (size_t)gr0 * C1 + c) = __nv_bfloat162(h0, h1);
            *reinterpret_cast<__nv_bfloat162*>(lo + (size_t)gr0 * C1 + c) = __nv_bfloat162(l0, l1);
            *reinterpret_cast<__nv_bfloat162*>(hi + (size_t)gr1 * C1 + c) = __nv_bfloat162(h2v, h3);
            *reinterpret_cast<__nv_bfloat162*>(lo + (size_t)gr1 * C1 + c) = __nv_bfloat162(l2v, l3);
        }
    }
}

// ---------------------------------------------------------------------------
// InstanceNorm1d per row; float4 loads; writes bf16 planes. C % 4 == 0.
// ---------------------------------------------------------------------------
__global__ void instnorm_kernel(float* __restrict__ p_in, int C,
                                bf16* __restrict__ hi, bf16* __restrict__ lo) {
    int row = blockIdx.x;
    const float4* p4 = reinterpret_cast<const float4*>(p_in + (size_t)row * C);
    int tid = threadIdx.x;
    int C4 = C >> 2;

    float s = 0.0f, q = 0.0f;
    for (int c = tid; c < C4; c += blockDim.x) {
        float4 v = p4[c];
        s += v.x + v.y + v.z + v.w;
        q += v.x * v.x + v.y * v.y + v.z * v.z + v.w * v.w;
    }
    __shared__ float ss[32], sq[32];
#pragma unroll
    for (int o = 16; o; o >>= 1) {
        s += __shfl_xor_sync(0xffffffffu, s, o);
        q += __shfl_xor_sync(0xffffffffu, q, o);
    }
    if ((tid & 31) == 0) { ss[tid >> 5] = s; sq[tid >> 5] = q; }
    __syncthreads();
    int nwarp = blockDim.x >> 5;
    if (tid < 32) {
        s = (tid < nwarp) ? ss[tid] : 0.0f;
        q = (tid < nwarp) ? sq[tid] : 0.0f;
#pragma unroll
        for (int o = 16; o; o >>= 1) {
            s += __shfl_xor_sync(0xffffffffu, s, o);
            q += __shfl_xor_sync(0xffffffffu, q, o);
        }
        if (tid == 0) { ss[0] = s; sq[0] = q; }
    }
    __syncthreads();
    float mean = ss[0] / C;
    float var = sq[0] / C - mean * mean;
    float inv = rsqrtf(var + EPS);
    __nv_bfloat162* h2p = reinterpret_cast<__nv_bfloat162*>(hi + (size_t)row * C);
    __nv_bfloat162* l2p = reinterpret_cast<__nv_bfloat162*>(lo + (size_t)row * C);
    for (int c = tid; c < C4; c += blockDim.x) {
        float4 v = p4[c];
        float n0 = (v.x - mean) * inv, n1 = (v.y - mean) * inv;
        float n2 = (v.z - mean) * inv, n3 = (v.w - mean) * inv;
        bf16 h0, l0, h1, l1, h2v, l2v, h3, l3;
        split_bf16(n0, h0, l0); split_bf16(n1, h1, l1);
        split_bf16(n2, h2v, l2v); split_bf16(n3, h3, l3);
        h2p[c * 2]     = __nv_bfloat162(h0, h1);
        h2p[c * 2 + 1] = __nv_bfloat162(h2v, h3);
        l2p[c * 2]     = __nv_bfloat162(l0, l1);
        l2p[c * 2 + 1] = __nv_bfloat162(l2v, l3);
    }
}

// ---------------------------------------------------------------------------
// Launch
// ---------------------------------------------------------------------------
static void launch_gemm(int M, int K, int Nout,
                        const bf16* Ahi, const bf16* Alo,
                        const bf16* Bhi, const bf16* Blo,
                        float* C, const float* rowscale, int do_leaky) {
    dim3 grid((Nout + GBN - 1) / GBN, M / GBM);
    bf16x3_gemm_kernel<<<grid, 256, GEMM_SMEM>>>(M, K, Nout, Ahi, Alo, Bhi, Blo,
                                                 C, rowscale, do_leaky);
}

extern "C" void kernel_launch(void* const* d_in, const int* in_sizes, int n_in,
                              void* d_out, int out_size) {
    const float* x    = (const float*)d_in[0];
    const float* ew   = (const float*)d_in[1];
    const int*   src  = (const int*)  d_in[2];
    const int*   dst  = (const int*)  d_in[3];
    const float* W1   = (const float*)d_in[4];
    const float* W2   = (const float*)d_in[5];
    const float* a1   = (const float*)d_in[6];
    const float* gm1  = (const float*)d_in[7];
    const float* bt1  = (const float*)d_in[8];
    const float* a2   = (const float*)d_in[9];
    const float* gm2  = (const float*)d_in[10];
    const float* bt2  = (const float*)d_in[11];
    const float* Win  = (const float*)d_in[12];
    const float* Whid = (const float*)d_in[13];
    const float* Wcls = (const float*)d_in[14];
    float* out = (float*)d_out;

    const int E = in_sizes[1];
    const int N = in_sizes[0] / F_IN;

    int *hs_p, *hd_p, *part_p, *bsum_p, *off_p, *cur_p;
    int2* edge_p;
    float *rs_out_p, *rs_in_p, *h2_p, *m1_p, *m2_p;
    bf16 *agg1_hi, *agg1_lo, *g1_hi, *g1_lo, *gn2_hi, *gn2_lo;
    bf16 *m1_hi, *m1_lo, *m2_hi, *m2_lo;
    bf16 *w1_hi, *w1_lo, *w2_hi, *w2_lo, *win_hi, *win_lo, *wh_hi, *wh_lo, *wc_hi, *wc_lo;
    cudaGetSymbolAddress((void**)&hs_p,    g_hist_src);
    cudaGetSymbolAddress((void**)&hd_p,    g_hist_dst);
    cudaGetSymbolAddress((void**)&part_p,  g_part);
    cudaGetSymbolAddress((void**)&bsum_p,  g_bsum);
    cudaGetSymbolAddress((void**)&off_p,   g_off);
    cudaGetSymbolAddress((void**)&cur_p,   g_cursor);
    cudaGetSymbolAddress((void**)&edge_p,  g_edge);
    cudaGetSymbolAddress((void**)&rs_out_p, g_rs_out);
    cudaGetSymbolAddress((void**)&rs_in_p,  g_rs_in);
    cudaGetSymbolAddress((void**)&h2_p,    g_h2);
    cudaGetSymbolAddress((void**)&m1_p,    g_m1);
    cudaGetSymbolAddress((void**)&m2_p,    g_m2);
    cudaGetSymbolAddress((void**)&agg1_hi, g_agg1_hi);
    cudaGetSymbolAddress((void**)&agg1_lo, g_agg1_lo);
    cudaGetSymbolAddress((void**)&g1_hi,   g_g1_hi);
    cudaGetSymbolAddress((void**)&g1_lo,   g_g1_lo);
    cudaGetSymbolAddress((void**)&gn2_hi,  g_gn2_hi);
    cudaGetSymbolAddress((void**)&gn2_lo,  g_gn2_lo);
    cudaGetSymbolAddress((void**)&m1_hi,   g_m1_hi);
    cudaGetSymbolAddress((void**)&m1_lo,   g_m1_lo);
    cudaGetSymbolAddress((void**)&m2_hi,   g_m2_hi);
    cudaGetSymbolAddress((void**)&m2_lo,   g_m2_lo);
    cudaGetSymbolAddress((void**)&w1_hi,   g_W1T_hi);
    cudaGetSymbolAddress((void**)&w1_lo,   g_W1T_lo);
    cudaGetSymbolAddress((void**)&w2_hi,   g_W2T_hi);
    cudaGetSymbolAddress((void**)&w2_lo,   g_W2T_lo);
    cudaGetSymbolAddress((void**)&win_hi,  g_WinT_hi);
    cudaGetSymbolAddress((void**)&win_lo,  g_WinT_lo);
    cudaGetSymbolAddress((void**)&wh_hi,   g_WhT_hi);
    cudaGetSymbolAddress((void**)&wh_lo,   g_WhT_lo);
    cudaGetSymbolAddress((void**)&wc_hi,   g_WcT_hi);
    cudaGetSymbolAddress((void**)&wc_lo,   g_WcT_lo);

    cudaFuncSetAttribute(bf16x3_gemm_kernel,
                         cudaFuncAttributeMaxDynamicSharedMemorySize, GEMM_SMEM);
    cudaFuncSetAttribute(gemm1_gn_kernel,
                         cudaFuncAttributeMaxDynamicSharedMemorySize, GEMM_SMEM);

    const int nb = N / 256;

    // --- CSR build ---
    zero_hist_kernel<<<(N + 255) / 256, 256>>>(hs_p, hd_p, N);
    hist_kernel<<<(E + 255) / 256, 256>>>(src, dst, E, hs_p, hd_p);
    scanA_kernel<<<nb, 256>>>(hd_p, part_p, bsum_p, N);
    scanB_kernel<<<1, 1024>>>(bsum_p, nb);
    scanC_kernel<<<(N + 255) / 256, 256>>>(part_p, bsum_p, off_p, cur_p,
                                           hs_p, hd_p, rs_out_p, rs_in_p, N, E);
    fill_kernel<<<(E + 255) / 256, 256>>>(dst, src, ew, rs_out_p, E, cur_p, edge_p);

    // --- conv1 gather -> bf16 planes ---
    gather1_kernel<<<(N + 7) / 8, 256>>>(x, edge_p, off_p, agg1_hi, agg1_lo, N);

    // --- weight transposes ---
    {
        dim3 b(32, 8);
        transpose_split_kernel<<<dim3(C1 / 32, F_IN / 32), b>>>(W1, w1_hi, w1_lo, F_IN, C1);
        transpose_split_kernel<<<dim3(C2 / 32, C1 / 32), b>>>(W2, w2_hi, w2_lo, C1, C2);
        transpose_split_kernel<<<dim3(HID / 32, IN_MLP / 32), b>>>(Win, win_hi, win_lo, IN_MLP, HID);
        transpose_split_kernel<<<dim3(HID4 / 32, HID / 32), b>>>(Whid, wh_hi, wh_lo, HID, HID4);
        transpose_split_kernel<<<dim3(OUTF / 32, HID4 / 32), b>>>(Wcls, wc_hi, wc_lo, HID4, OUTF);
    }

    // --- GEMM1 with fused rs_in/leaky/graphnorm1 -> g1 planes ---
    {
        dim3 grid(1, N / GBM);
        gemm1_gn_kernel<<<grid, 256, GEMM_SMEM>>>(agg1_hi, agg1_lo, w1_hi, w1_lo,
                                                  rs_in_p, a1, gm1, bt1,
                                                  g1_hi, g1_lo);
    }

    // --- GEMM2 -> h2 fp32, then fused gather2+graphnorm2 -> gn2 planes ---
    launch_gemm(N, C1, C2, g1_hi, g1_lo, w2_hi, w2_lo, h2_p, nullptr, 0);
    gather2_gn_kernel<<<BATCH, 256>>>(h2_p, edge_p, off_p, rs_in_p,
                                      a2, gm2, bt2, gn2_hi, gn2_lo);

    // --- MLP1 + instnorm ---
    launch_gemm(BATCH, IN_MLP, HID, gn2_hi, gn2_lo, win_hi, win_lo, m1_p, nullptr, 1);
    instnorm_kernel<<<BATCH, 256>>>(m1_p, HID, m1_hi, m1_lo);

    // --- MLP2 + instnorm ---
    launch_gemm(BATCH, HID, HID4, m1_hi, m1_lo, wh_hi, wh_lo, m2_p, nullptr, 1);
    instnorm_kernel<<<BATCH, 256>>>(m2_p, HID4, m2_hi, m2_lo);

    // --- MLP3 (bf16x3) -> out ---
    launch_gemm(BATCH, HID4, OUTF, m2_hi, m2_lo, wc_hi, wc_lo, out, nullptr, 0);
}

// round 13
// speedup vs baseline: 1.0099x; 1.0099x over previous
#include <cuda_runtime.h>
#include <cuda_bf16.h>
#include <cstdint>
#include <math.h>

// ---------------------------------------------------------------------------
// Problem constants
// ---------------------------------------------------------------------------
#define NN       262144
#define NE       2097152
#define F_IN     64
#define C1       128
#define C2       96
#define BATCH    4096
#define NODES    64
#define IN_MLP   6144
#define HID      2048
#define HID4     512
#define OUTF     256
#define NEG_SLOPE 0.01f
#define EPS      1e-5f

typedef __nv_bfloat16 bf16;

// ---------------------------------------------------------------------------
// Scratch
// ---------------------------------------------------------------------------
__device__ int   g_hist_src[NN];
__device__ int   g_hist_dst[NN];
__device__ int   g_part    [NN];
__device__ int   g_bsum    [NN / 256];
__device__ int   g_off     [NN + 1];
__device__ int   g_cursor  [NN];
__device__ int2  g_edge    [NE];          // (src, ew*rs_out[src]) sorted by dst
__device__ float g_rs_out  [NN];
__device__ float g_rs_in   [NN];
__device__ float g_h2      [(size_t)NN * C2];
__device__ float g_m1      [(size_t)BATCH * HID];
__device__ float g_m2      [(size_t)BATCH * HID4];
// bf16 hi/lo split planes
__device__ bf16 g_agg1_hi[(size_t)NN * F_IN];
__device__ bf16 g_agg1_lo[(size_t)NN * F_IN];
__device__ bf16 g_g1_hi  [(size_t)NN * C1];
__device__ bf16 g_g1_lo  [(size_t)NN * C1];
__device__ bf16 g_gn2_hi [(size_t)NN * C2];
__device__ bf16 g_gn2_lo [(size_t)NN * C2];
__device__ bf16 g_m1_hi  [(size_t)BATCH * HID];
__device__ bf16 g_m1_lo  [(size_t)BATCH * HID];
__device__ bf16 g_m2_hi  [(size_t)BATCH * HID4];
__device__ bf16 g_m2_lo  [(size_t)BATCH * HID4];
// transposed split weights
__device__ bf16 g_W1T_hi [C1 * F_IN];
__device__ bf16 g_W1T_lo [C1 * F_IN];
__device__ bf16 g_W2T_hi [128 * C1];
__device__ bf16 g_W2T_lo [128 * C1];
__device__ bf16 g_WinT_hi[(size_t)HID * IN_MLP];
__device__ bf16 g_WinT_lo[(size_t)HID * IN_MLP];
__device__ bf16 g_WhT_hi [(size_t)HID4 * HID];
__device__ bf16 g_WhT_lo [(size_t)HID4 * HID];
__device__ bf16 g_WcT_hi [OUTF * HID4];
__device__ bf16 g_WcT_lo [OUTF * HID4];

// ---------------------------------------------------------------------------
// Helpers
// ---------------------------------------------------------------------------
__device__ __forceinline__ void cp_async16(uint32_t dst, const void* src) {
    asm volatile("cp.async.cg.shared.global [%0], [%1], 16;" :: "r"(dst), "l"(src));
}

__device__ __forceinline__ uint32_t smem_u32(const void* p) {
    uint32_t r;
    asm("{ .reg .u64 t; cvta.to.shared.u64 t, %1; cvt.u32.u64 %0, t; }"
        : "=r"(r) : "l"(p));
    return r;
}

__device__ __forceinline__ void mma_bf16(float (&d)[4], const uint32_t (&a)[4],
                                         const uint32_t (&b)[2]) {
    asm volatile(
        "mma.sync.aligned.m16n8k16.row.col.f32.bf16.bf16.f32 "
        "{%0,%1,%2,%3}, {%4,%5,%6,%7}, {%8,%9}, {%0,%1,%2,%3};"
        : "+f"(d[0]), "+f"(d[1]), "+f"(d[2]), "+f"(d[3])
        : "r"(a[0]), "r"(a[1]), "r"(a[2]), "r"(a[3]), "r"(b[0]), "r"(b[1]));
}

__device__ __forceinline__ void ldsm_x4(uint32_t (&r)[4], uint32_t addr) {
    asm volatile("ldmatrix.sync.aligned.m8n8.x4.shared.b16 {%0,%1,%2,%3}, [%4];"
                 : "=r"(r[0]), "=r"(r[1]), "=r"(r[2]), "=r"(r[3]) : "r"(addr));
}

__device__ __forceinline__ void split_bf16(float v, bf16& h, bf16& l) {
    h = __float2bfloat16(v);
    l = __float2bfloat16(v - __bfloat162float(h));
}

__device__ __forceinline__ float leaky(float v) {
    return (v >= 0.0f) ? v : NEG_SLOPE * v;
}

// ---------------------------------------------------------------------------
// CSR build
// ---------------------------------------------------------------------------
__global__ void zero_hist_kernel(int* __restrict__ a, int* __restrict__ b, int n) {
    int i = blockIdx.x * blockDim.x + threadIdx.x;
    if (i < n) { a[i] = 0; b[i] = 0; }
}

__global__ void hist_kernel(const int* __restrict__ src, const int* __restrict__ dst,
                            int E, int* __restrict__ hs, int* __restrict__ hd) {
    int i = blockIdx.x * blockDim.x + threadIdx.x;
    if (i < E) {
        atomicAdd(&hs[src[i]], 1);
        atomicAdd(&hd[dst[i]], 1);
    }
}

__global__ void scanA_kernel(const int* __restrict__ h, int* __restrict__ part,
                             int* __restrict__ bsum, int n) {
    __shared__ int wsum[8];
    int i = blockIdx.x * 256 + threadIdx.x;
    int t = threadIdx.x, lane = t & 31, w = t >> 5;
    int v = (i < n) ? h[i] : 0;
    int inc = v;
#pragma unroll
    for (int o = 1; o < 32; o <<= 1) {
        int u = __shfl_up_sync(0xffffffffu, inc, o);
        if (lane >= o) inc += u;
    }
    if (lane == 31) wsum[w] = inc;
    __syncthreads();
    if (w == 0) {
        int s = (lane < 8) ? wsum[lane] : 0;
#pragma unroll
        for (int o = 1; o < 8; o <<= 1) {
            int u = __shfl_up_sync(0xffffffffu, s, o);
            if (lane >= o) s += u;
        }
        if (lane < 8) wsum[lane] = s;
    }
    __syncthreads();
    int base = (w > 0) ? wsum[w - 1] : 0;
    if (i < n) part[i] = base + inc - v;
    if (t == 255) bsum[blockIdx.x] = base + inc;
}

__global__ void scanB_kernel(int* __restrict__ bsum, int nb) {
    __shared__ int wsum[32];
    int t = threadIdx.x, lane = t & 31, w = t >> 5;
    int v = (t < nb) ? bsum[t] : 0;
    int inc = v;
#pragma unroll
    for (int o = 1; o < 32; o <<= 1) {
        int u = __shfl_up_sync(0xffffffffu, inc, o);
        if (lane >= o) inc += u;
    }
    if (lane == 31) wsum[w] = inc;
    __syncthreads();
    if (w == 0) {
        int s = wsum[lane];
#pragma unroll
        for (int o = 1; o < 32; o <<= 1) {
            int u = __shfl_up_sync(0xffffffffu, s, o);
            if (lane >= o) s += u;
        }
        wsum[lane] = s;
    }
    __syncthreads();
    int base = (w > 0) ? wsum[w - 1] : 0;
    if (t < nb) bsum[t] = base + inc - v;
}

// scanC: offsets + cursors, and fused rsqrt-degree computation.
__global__ void scanC_kernel(const int* __restrict__ part, const int* __restrict__ bsum,
                             int* __restrict__ off, int* __restrict__ cursor,
                             const int* __restrict__ hs, const int* __restrict__ hd,
                             float* __restrict__ rso, float* __restrict__ rsi,
                             int n, int E) {
    int i = blockIdx.x * blockDim.x + threadIdx.x;
    if (i < n) {
        int o = part[i] + bsum[i >> 8];
        off[i] = o;
        cursor[i] = o;
        rso[i] = rsqrtf(fmaxf((float)hs[i], 1.0f));
        rsi[i] = rsqrtf(fmaxf((float)hd[i], 1.0f));
    }
    if (i == 0) off[n] = E;
}

// fill: pack (src, ew*rs_out[src]) per edge into dst-sorted order.
__global__ void fill_kernel(const int* __restrict__ dst, const int* __restrict__ src,
                            const float* __restrict__ ew, const float* __restrict__ rs_out,
                            int E, int* __restrict__ cursor, int2* __restrict__ edge) {
    int i = blockIdx.x * blockDim.x + threadIdx.x;
    if (i < E) {
        int s = src[i];
        float w = ew[i] * rs_out[s];
        int p = atomicAdd(&cursor[dst[i]], 1);
        edge[p] = make_int2(s, __float_as_int(w));
    }
}

// ---------------------------------------------------------------------------
// gather1: agg1[d] = sum_e x[src] * w_packed; writes bf16 planes. Warp/node.
// ---------------------------------------------------------------------------
__global__ void gather1_kernel(const float* __restrict__ x, const int2* __restrict__ edge,
                               const int* __restrict__ off,
                               bf16* __restrict__ hi, bf16* __restrict__ lo, int n) {
    int d = blockIdx.x * 8 + (threadIdx.x >> 5);
    if (d >= n) return;
    int lane = threadIdx.x & 31;
    int j0 = off[d], j1 = off[d + 1];
    float2 acc = make_float2(0.0f, 0.0f);
    int j = j0;
    for (; j + 1 < j1; j += 2) {
        int2 e0 = edge[j], e1 = edge[j + 1];
        float w0 = __int_as_float(e0.y), w1 = __int_as_float(e1.y);
        float2 v0 = reinterpret_cast<const float2*>(x)[(size_t)e0.x * 32 + lane];
        float2 v1 = reinterpret_cast<const float2*>(x)[(size_t)e1.x * 32 + lane];
        acc.x = fmaf(v0.x, w0, acc.x);
        acc.y = fmaf(v0.y, w0, acc.y);
        acc.x = fmaf(v1.x, w1, acc.x);
        acc.y = fmaf(v1.y, w1, acc.y);
    }
    if (j < j1) {
        int2 e = edge[j];
        float w = __int_as_float(e.y);
        float2 v = reinterpret_cast<const float2*>(x)[(size_t)e.x * 32 + lane];
        acc.x = fmaf(v.x, w, acc.x);
        acc.y = fmaf(v.y, w, acc.y);
    }
    bf16 h0, l0, h1, l1;
    split_bf16(acc.x, h0, l0);
    split_bf16(acc.y, h1, l1);
    reinterpret_cast<__nv_bfloat162*>(hi)[(size_t)d * 32 + lane] = __nv_bfloat162(h0, h1);
    reinterpret_cast<__nv_bfloat162*>(lo)[(size_t)d * 32 + lane] = __nv_bfloat162(l0, l1);
}

// ---------------------------------------------------------------------------
// Fused gather2 + graphnorm2: one block per graph (64 nodes x 96 feats).
// ---------------------------------------------------------------------------
__global__ __launch_bounds__(256)
void gather2_gn_kernel(const float* __restrict__ h2, const int2* __restrict__ edge,
                       const int* __restrict__ off, const float* __restrict__ rs_in,
                       const float* __restrict__ alpha, const float* __restrict__ gamma,
                       const float* __restrict__ beta,
                       bf16* __restrict__ hi, bf16* __restrict__ lo) {
    __shared__ float sm[NODES * C2];
    __shared__ float s_scale[C2], s_bias[C2];
    int g = blockIdx.x;
    int wid = threadIdx.x >> 5, lane = threadIdx.x & 31;

    // phase 1: gather + rs_in + leaky into smem
    for (int nl = wid; nl < NODES; nl += 8) {
        int d = g * NODES + nl;
        int j0 = off[d], j1 = off[d + 1];
        float a0 = 0.0f, a1 = 0.0f, a2 = 0.0f;
        int j = j0;
        for (; j + 1 < j1; j += 2) {
            int2 e0 = edge[j], e1 = edge[j + 1];
            float w0 = __int_as_float(e0.y), w1 = __int_as_float(e1.y);
            const float* hp0 = h2 + (size_t)e0.x * 96;
            const float* hp1 = h2 + (size_t)e1.x * 96;
            a0 = fmaf(hp0[lane], w0, a0);
            a1 = fmaf(hp0[lane + 32], w0, a1);
            a2 = fmaf(hp0[lane + 64], w0, a2);
            a0 = fmaf(hp1[lane], w1, a0);
            a1 = fmaf(hp1[lane + 32], w1, a1);
            a2 = fmaf(hp1[lane + 64], w1, a2);
        }
        if (j < j1) {
            int2 e = edge[j];
            float w = __int_as_float(e.y);
            const float* hp = h2 + (size_t)e.x * 96;
            a0 = fmaf(hp[lane], w, a0);
            a1 = fmaf(hp[lane + 32], w, a1);
            a2 = fmaf(hp[lane + 64], w, a2);
        }
        float ri = rs_in[d];
        sm[nl * 96 + lane]      = leaky(a0 * ri);
        sm[nl * 96 + lane + 32] = leaky(a1 * ri);
        sm[nl * 96 + lane + 64] = leaky(a2 * ri);
    }
    __syncthreads();

    // phase 2: per-channel stats -> folded scale/bias
    int c = threadIdx.x;
    if (c < C2) {
        float sum = 0.0f;
#pragma unroll 8
        for (int r = 0; r < NODES; r++) sum += sm[r * C2 + c];
        float mean = sum * (1.0f / NODES);
        float am = alpha[c] * mean;
        float var = 0.0f;
#pragma unroll 8
        for (int r = 0; r < NODES; r++) {
            float s = sm[r * C2 + c] - am;
            var += s * s;
        }
        var *= (1.0f / NODES);
        float inv = rsqrtf(var + EPS);
        float gmm = gamma[c];
        s_scale[c] = gmm * inv;
        s_bias[c]  = beta[c] - gmm * am * inv;
    }
    __syncthreads();

    // phase 3: coalesced row-major emission
    size_t obase = (size_t)g * NODES * C2;
    __nv_bfloat162* h2p = reinterpret_cast<__nv_bfloat162*>(hi + obase);
    __nv_bfloat162* l2p = reinterpret_cast<__nv_bfloat162*>(lo + obase);
    for (int idx = threadIdx.x; idx < (NODES * C2) / 2; idx += 256) {
        int e0 = idx * 2;
        int c0 = e0 % C2;
        float v0 = fmaf(sm[e0],     s_scale[c0],     s_bias[c0]);
        float v1 = fmaf(sm[e0 + 1], s_scale[c0 + 1], s_bias[c0 + 1]);
        bf16 h0, l0, h1, l1;
        split_bf16(v0, h0, l0);
        split_bf16(v1, h1, l1);
        h2p[idx] = __nv_bfloat162(h0, h1);
        l2p[idx] = __nv_bfloat162(l0, l1);
    }
}

// ---------------------------------------------------------------------------
// Transpose in[R,C] -> hi/lo[C,R] bf16 split planes.
// ---------------------------------------------------------------------------
__global__ void transpose_split_kernel(const float* __restrict__ in,
                                       bf16* __restrict__ hi, bf16* __restrict__ lo,
                                       int R, int C) {
    __shared__ float t[32][33];
    int c0 = blockIdx.x * 32, r0 = blockIdx.y * 32;
    int x = threadIdx.x, y = threadIdx.y;
#pragma unroll
    for (int dy = 0; dy < 32; dy += 8) {
        int r = r0 + y + dy, c = c0 + x;
        t[y + dy][x] = (r < R && c < C) ? in[(size_t)r * C + c] : 0.0f;
    }
    __syncthreads();
#pragma unroll
    for (int dy = 0; dy < 32; dy += 8) {
        int oc = c0 + y + dy, orr = r0 + x;
        if (oc < C && orr < R) {
            bf16 h, l;
            split_bf16(t[x][y + dy], h, l);
            hi[(size_t)oc * R + orr] = h;
            lo[(size_t)oc * R + orr] = l;
        }
    }
}

// ---------------------------------------------------------------------------
// bf16x3 mma.sync GEMM core -- fragment loads via ldmatrix.x4
// ---------------------------------------------------------------------------
#define GBM 256
#define GBN 128
#define GBK 32
#define ROWB 80
#define A_PLANE (GBM * ROWB)
#define B_PLANE (GBN * ROWB)
#define OFF_AHI 0
#define OFF_ALO (A_PLANE)
#define OFF_BHI (2 * A_PLANE)
#define OFF_BLO (2 * A_PLANE + B_PLANE)
#define STAGE_B (2 * A_PLANE + 2 * B_PLANE)
#define GEMM_SMEM (3 * STAGE_B)

__device__ __forceinline__ void gemm_load_stage(const bf16* __restrict__ Ahi,
                                                const bf16* __restrict__ Alo,
                                                const bf16* __restrict__ Bhi,
                                                const bf16* __restrict__ Blo,
                                                int K, int m0, int n0, int k0,
                                                uint32_t sbuf, int tid) {
#pragma unroll
    for (int p = 0; p < 4; p++) {
        int id = tid + (p << 8);
        int r = id >> 2, c = id & 3;
        size_t g = (size_t)(m0 + r) * K + k0 + c * 8;
        uint32_t o = r * ROWB + c * 16;
        cp_async16(sbuf + OFF_AHI + o, Ahi + g);
        cp_async16(sbuf + OFF_ALO + o, Alo + g);
    }
#pragma unroll
    for (int p = 0; p < 2; p++) {
        int id = tid + (p << 8);
        int r = id >> 2, c = id & 3;
        size_t g = (size_t)(n0 + r) * K + k0 + c * 8;
        uint32_t o = r * ROWB + c * 16;
        cp_async16(sbuf + OFF_BHI + o, Bhi + g);
        cp_async16(sbuf + OFF_BLO + o, Blo + g);
    }
}

// Mainloop producing acc[4][8][4]; expects sbase, tid, wid, lane, warp_m,
// warp_n, m0, n0, K, T in scope. Fragment loads via ldmatrix (conflict-free
// on the 80B row stride).
#define GEMM_MAINLOOP(Ahi, Alo, Bhi, Blo)                                        \
    _Pragma("unroll")                                                            \
    for (int s = 0; s < 2; s++) {                                                \
        if (s < T) gemm_load_stage(Ahi, Alo, Bhi, Blo, K, m0, n0, s * GBK,       \
                                   sbase + s * STAGE_B, tid);                    \
        asm volatile("cp.async.commit_group;" ::: "memory");                     \
    }                                                                            \
    {                                                                            \
        const int a_row  = (lane & 7) + ((lane >> 3) & 1) * 8;                   \
        const uint32_t a_koff = ((uint32_t)(lane >> 4)) * 16;                    \
        const int b_row  = (lane & 7) + ((lane >> 4) & 1) * 8;                   \
        const uint32_t b_koff = ((uint32_t)((lane >> 3) & 1)) * 16;              \
        for (int i = 0; i < T; i++) {                                            \
            if (i + 1 < T) asm volatile("cp.async.wait_group 1;" ::: "memory");  \
            else           asm volatile("cp.async.wait_group 0;" ::: "memory");  \
            __syncthreads();                                                     \
            if (i + 2 < T)                                                       \
                gemm_load_stage(Ahi, Alo, Bhi, Blo, K, m0, n0, (i + 2) * GBK,    \
                                sbase + ((i + 2) % 3) * STAGE_B, tid);           \
            asm volatile("cp.async.commit_group;" ::: "memory");                 \
            const uint32_t sbu = sbase + (i % 3) * STAGE_B;                      \
            _Pragma("unroll")                                                    \
            for (int ks = 0; ks < 2; ks++) {                                     \
                const uint32_t kbase = (uint32_t)(ks * 32);                      \
                uint32_t ahi[4][4], alo[4][4];                                   \
                _Pragma("unroll")                                                \
                for (int mt = 0; mt < 4; mt++) {                                 \
                    uint32_t ar = (uint32_t)(warp_m * 64 + mt * 16 + a_row);     \
                    uint32_t aaddr = sbu + OFF_AHI + ar * ROWB + kbase + a_koff; \
                    ldsm_x4(ahi[mt], aaddr);                                     \
                    ldsm_x4(alo[mt], aaddr + (OFF_ALO - OFF_AHI));               \
                }                                                                \
                uint32_t bhi[8][2], blo[8][2];                                   \
                _Pragma("unroll")                                                \
                for (int p = 0; p < 4; p++) {                                    \
                    uint32_t br = (uint32_t)(warp_n * 64 + p * 16 + b_row);      \
                    uint32_t baddr = sbu + OFF_BHI + br * ROWB + kbase + b_koff; \
                    uint32_t th[4], tl[4];                                       \
                    ldsm_x4(th, baddr);                                          \
                    ldsm_x4(tl, baddr + (OFF_BLO - OFF_BHI));                    \
                    bhi[p * 2][0] = th[0]; bhi[p * 2][1] = th[1];                \
                    bhi[p * 2 + 1][0] = th[2]; bhi[p * 2 + 1][1] = th[3];        \
                    blo[p * 2][0] = tl[0]; blo[p * 2][1] = tl[1];                \
                    blo[p * 2 + 1][0] = tl[2]; blo[p * 2 + 1][1] = tl[3];        \
                }                                                                \
                _Pragma("unroll")                                                \
                for (int mt = 0; mt < 4; mt++)                                   \
                    _Pragma("unroll")                                            \
                    for (int nt = 0; nt < 8; nt++) {                             \
                        float (&d)[4] = acc[mt][nt];                             \
                        mma_bf16(d, ahi[mt], bhi[nt]);                           \
                        mma_bf16(d, ahi[mt], blo[nt]);                           \
                        mma_bf16(d, alo[mt], bhi[nt]);                           \
                    }                                                            \
            }                                                                    \
        }                                                                        \
    }

// Generic GEMM: fp32 C output, optional rowscale + leaky.
__global__ __launch_bounds__(256, 1)
void bf16x3_gemm_kernel(int M, int K, int Nout,
                        const bf16* __restrict__ Ahi, const bf16* __restrict__ Alo,
                        const bf16* __restrict__ Bhi, const bf16* __restrict__ Blo,
                        float* __restrict__ C,
                        const float* __restrict__ rowscale, int do_leaky) {
    extern __shared__ char dynsm[];
    const uint32_t sbase = smem_u32(dynsm);
    const int tid = threadIdx.x, wid = tid >> 5, lane = tid & 31;
    const int warp_m = wid & 3, warp_n = wid >> 2;
    const int m0 = blockIdx.y * GBM, n0 = blockIdx.x * GBN;

    float acc[4][8][4];
#pragma unroll
    for (int mt = 0; mt < 4; mt++)
#pragma unroll
        for (int nt = 0; nt < 8; nt++)
#pragma unroll
            for (int j = 0; j < 4; j++) acc[mt][nt][j] = 0.0f;

    const int T = K / GBK;
    GEMM_MAINLOOP(Ahi, Alo, Bhi, Blo)

#pragma unroll
    for (int mt = 0; mt < 4; mt++) {
        const int r0 = m0 + warp_m * 64 + mt * 16 + (lane >> 2);
        const int r1 = r0 + 8;
        const float s0 = rowscale ? rowscale[r0] : 1.0f;
        const float s1 = rowscale ? rowscale[r1] : 1.0f;
#pragma unroll
        for (int nt = 0; nt < 8; nt++) {
            const int c = n0 + warp_n * 64 + nt * 8 + (lane & 3) * 2;
            if (c < Nout) {
                float v0 = acc[mt][nt][0] * s0;
                float v1 = acc[mt][nt][1] * s0;
                float v2 = acc[mt][nt][2] * s1;
                float v3 = acc[mt][nt][3] * s1;
                if (do_leaky) { v0 = leaky(v0); v1 = leaky(v1); v2 = leaky(v2); v3 = leaky(v3); }
                *reinterpret_cast<float2*>(C + (size_t)r0 * Nout + c) = make_float2(v0, v1);
                *reinterpret_cast<float2*>(C + (size_t)r1 * Nout + c) = make_float2(v2, v3);
            }
        }
    }
}

// GEMM1 + fused graphnorm1 (rs_out lives in the edge weights).
__global__ __launch_bounds__(256, 1)
void gemm1_gn_kernel(const bf16* __restrict__ Ahi, const bf16* __restrict__ Alo,
                     const bf16* __restrict__ Bhi, const bf16* __restrict__ Blo,
                     const float* __restrict__ rs_in,
                     const float* __restrict__ alpha, const float* __restrict__ gamma,
                     const float* __restrict__ beta,
                     bf16* __restrict__ hi, bf16* __restrict__ lo) {
    extern __shared__ char dynsm[];
    const uint32_t sbase = smem_u32(dynsm);
    const int tid = threadIdx.x, wid = tid >> 5, lane = tid & 31;
    const int warp_m = wid & 3, warp_n = wid >> 2;
    const int m0 = blockIdx.y * GBM, n0 = 0;
    const int K = F_IN;

    float acc[4][8][4];
#pragma unroll
    for (int mt = 0; mt < 4; mt++)
#pragma unroll
        for (int nt = 0; nt < 8; nt++)
#pragma unroll
            for (int j = 0; j < 4; j++) acc[mt][nt][j] = 0.0f;

    const int T = K / GBK;   // 2
    GEMM_MAINLOOP(Ahi, Alo, Bhi, Blo)

    // pre-op: v = leaky(acc * rs_in[row])
#pragma unroll
    for (int mt = 0; mt < 4; mt++) {
        const int gr0 = m0 + warp_m * 64 + mt * 16 + (lane >> 2);
        const float ri0 = rs_in[gr0], ri1 = rs_in[gr0 + 8];
#pragma unroll
        for (int nt = 0; nt < 8; nt++) {
            acc[mt][nt][0] = leaky(acc[mt][nt][0] * ri0);
            acc[mt][nt][1] = leaky(acc[mt][nt][1] * ri0);
            acc[mt][nt][2] = leaky(acc[mt][nt][2] * ri1);
            acc[mt][nt][3] = leaky(acc[mt][nt][3] * ri1);
        }
    }

    // column stats over this warp's 64 rows
    const int cbase = warp_n * 64 + (lane & 3) * 2;
    float am0[8], am1[8], inv0[8], inv1[8];
#pragma unroll
    for (int nt = 0; nt < 8; nt++) {
        float s0 = 0.0f, s1 = 0.0f;
#pragma unroll
        for (int mt = 0; mt < 4; mt++) {
            s0 += acc[mt][nt][0] + acc[mt][nt][2];
            s1 += acc[mt][nt][1] + acc[mt][nt][3];
        }
#pragma unroll
        for (int o = 4; o <= 16; o <<= 1) {
            s0 += __shfl_xor_sync(0xffffffffu, s0, o);
            s1 += __shfl_xor_sync(0xffffffffu, s1, o);
        }
        const int c = cbase + nt * 8;
        float2 al = *reinterpret_cast<const float2*>(alpha + c);
        am0[nt] = al.x * s0 * (1.0f / NODES);
        am1[nt] = al.y * s1 * (1.0f / NODES);

        float q0 = 0.0f, q1 = 0.0f;
#pragma unroll
        for (int mt = 0; mt < 4; mt++) {
            float d0 = acc[mt][nt][0] - am0[nt], d2 = acc[mt][nt][2] - am0[nt];
            float d1 = acc[mt][nt][1] - am1[nt], d3 = acc[mt][nt][3] - am1[nt];
            q0 += d0 * d0 + d2 * d2;
            q1 += d1 * d1 + d3 * d3;
        }
#pragma unroll
        for (int o = 4; o <= 16; o <<= 1) {
            q0 += __shfl_xor_sync(0xffffffffu, q0, o);
            q1 += __shfl_xor_sync(0xffffffffu, q1, o);
        }
        inv0[nt] = rsqrtf(q0 * (1.0f / NODES) + EPS);
        inv1[nt] = rsqrtf(q1 * (1.0f / NODES) + EPS);
    }

    // normalize, split, store planes
#pragma unroll
    for (int mt = 0; mt < 4; mt++) {
        const int gr0 = m0 + warp_m * 64 + mt * 16 + (lane >> 2);
        const int gr1 = gr0 + 8;
#pragma unroll
        for (int nt = 0; nt < 8; nt++) {
            const int c = cbase + nt * 8;
            float2 gm = *reinterpret_cast<const float2*>(gamma + c);
            float2 bt = *reinterpret_cast<const float2*>(beta + c);
            float o0 = gm.x * (acc[mt][nt][0] - am0[nt]) * inv0[nt] + bt.x;
            float o1 = gm.y * (acc[mt][nt][1] - am1[nt]) * inv1[nt] + bt.y;
            float o2 = gm.x * (acc[mt][nt][2] - am0[nt]) * inv0[nt] + bt.x;
            float o3 = gm.y * (acc[mt][nt][3] - am1[nt]) * inv1[nt] + bt.y;
            bf16 h0, l0, h1, l1, h2v, l2v, h3, l3;
            split_bf16(o0, h0, l0); split_bf16(o1, h1, l1);
            split_bf16(o2, h2v, l2v); split_bf16(o3, h3, l3);
            *reinterpret_cast<__nv_bfloat162*>(hi + (size_t)gr0 * C1 + c) = __nv_bfloat162(h0, h1);
            *reinterpret_cast<__nv_bfloat162*>(lo + (size_t)gr0 * C1 + c) = __nv_bfloat162(l0, l1);
            *reinterpret_cast<__nv_bfloat162*>(hi + (size_t)gr1 * C1 + c) = __nv_bfloat162(h2v, h3);
            *reinterpret_cast<__nv_bfloat162*>(lo + (size_t)gr1 * C1 + c) = __nv_bfloat162(l2v, l3);
        }
    }
}

// ---------------------------------------------------------------------------
// InstanceNorm1d per row; float4 loads; writes bf16 planes. C % 4 == 0.
// ---------------------------------------------------------------------------
__global__ void instnorm_kernel(float* __restrict__ p_in, int C,
                                bf16* __restrict__ hi, bf16* __restrict__ lo) {
    int row = blockIdx.x;
    const float4* p4 = reinterpret_cast<const float4*>(p_in + (size_t)row * C);
    int tid = threadIdx.x;
    int C4 = C >> 2;

    float s = 0.0f, q = 0.0f;
    for (int c = tid; c < C4; c += blockDim.x) {
        float4 v = p4[c];
        s += v.x + v.y + v.z + v.w;
        q += v.x * v.x + v.y * v.y + v.z * v.z + v.w * v.w;
    }
    __shared__ float ss[32], sq[32];
#pragma unroll
    for (int o = 16; o; o >>= 1) {
        s += __shfl_xor_sync(0xffffffffu, s, o);
        q += __shfl_xor_sync(0xffffffffu, q, o);
    }
    if ((tid & 31) == 0) { ss[tid >> 5] = s; sq[tid >> 5] = q; }
    __syncthreads();
    int nwarp = blockDim.x >> 5;
    if (tid < 32) {
        s = (tid < nwarp) ? ss[tid] : 0.0f;
        q = (tid < nwarp) ? sq[tid] : 0.0f;
#pragma unroll
        for (int o = 16; o; o >>= 1) {
            s += __shfl_xor_sync(0xffffffffu, s, o);
            q += __shfl_xor_sync(0xffffffffu, q, o);
        }
        if (tid == 0) { ss[0] = s; sq[0] = q; }
    }
    __syncthreads();
    float mean = ss[0] / C;
    float var = sq[0] / C - mean * mean;
    float inv = rsqrtf(var + EPS);
    __nv_bfloat162* h2p = reinterpret_cast<__nv_bfloat162*>(hi + (size_t)row * C);
    __nv_bfloat162* l2p = reinterpret_cast<__nv_bfloat162*>(lo + (size_t)row * C);
    for (int c = tid; c < C4; c += blockDim.x) {
        float4 v = p4[c];
        float n0 = (v.x - mean) * inv, n1 = (v.y - mean) * inv;
        float n2 = (v.z - mean) * inv, n3 = (v.w - mean) * inv;
        bf16 h0, l0, h1, l1, h2v, l2v, h3, l3;
        split_bf16(n0, h0, l0); split_bf16(n1, h1, l1);
        split_bf16(n2, h2v, l2v); split_bf16(n3, h3, l3);
        h2p[c * 2]     = __nv_bfloat162(h0, h1);
        h2p[c * 2 + 1] = __nv_bfloat162(h2v, h3);
        l2p[c * 2]     = __nv_bfloat162(l0, l1);
        l2p[c * 2 + 1] = __nv_bfloat162(l2v, l3);
    }
}

// ---------------------------------------------------------------------------
// Launch
// ---------------------------------------------------------------------------
static void launch_gemm(int M, int K, int Nout,
                        const bf16* Ahi, const bf16* Alo,
                        const bf16* Bhi, const bf16* Blo,
                        float* C, const float* rowscale, int do_leaky) {
    dim3 grid((Nout + GBN - 1) / GBN, M / GBM);
    bf16x3_gemm_kernel<<<grid, 256, GEMM_SMEM>>>(M, K, Nout, Ahi, Alo, Bhi, Blo,
                                                 C, rowscale, do_leaky);
}

extern "C" void kernel_launch(void* const* d_in, const int* in_sizes, int n_in,
                              void* d_out, int out_size) {
    const float* x    = (const float*)d_in[0];
    const float* ew   = (const float*)d_in[1];
    const int*   src  = (const int*)  d_in[2];
    const int*   dst  = (const int*)  d_in[3];
    const float* W1   = (const float*)d_in[4];
    const float* W2   = (const float*)d_in[5];
    const float* a1   = (const float*)d_in[6];
    const float* gm1  = (const float*)d_in[7];
    const float* bt1  = (const float*)d_in[8];
    const float* a2   = (const float*)d_in[9];
    const float* gm2  = (const float*)d_in[10];
    const float* bt2  = (const float*)d_in[11];
    const float* Win  = (const float*)d_in[12];
    const float* Whid = (const float*)d_in[13];
    const float* Wcls = (const float*)d_in[14];
    float* out = (float*)d_out;

    const int E = in_sizes[1];
    const int N = in_sizes[0] / F_IN;

    int *hs_p, *hd_p, *part_p, *bsum_p, *off_p, *cur_p;
    int2* edge_p;
    float *rs_out_p, *rs_in_p, *h2_p, *m1_p, *m2_p;
    bf16 *agg1_hi, *agg1_lo, *g1_hi, *g1_lo, *gn2_hi, *gn2_lo;
    bf16 *m1_hi, *m1_lo, *m2_hi, *m2_lo;
    bf16 *w1_hi, *w1_lo, *w2_hi, *w2_lo, *win_hi, *win_lo, *wh_hi, *wh_lo, *wc_hi, *wc_lo;
    cudaGetSymbolAddress((void**)&hs_p,    g_hist_src);
    cudaGetSymbolAddress((void**)&hd_p,    g_hist_dst);
    cudaGetSymbolAddress((void**)&part_p,  g_part);
    cudaGetSymbolAddress((void**)&bsum_p,  g_bsum);
    cudaGetSymbolAddress((void**)&off_p,   g_off);
    cudaGetSymbolAddress((void**)&cur_p,   g_cursor);
    cudaGetSymbolAddress((void**)&edge_p,  g_edge);
    cudaGetSymbolAddress((void**)&rs_out_p, g_rs_out);
    cudaGetSymbolAddress((void**)&rs_in_p,  g_rs_in);
    cudaGetSymbolAddress((void**)&h2_p,    g_h2);
    cudaGetSymbolAddress((void**)&m1_p,    g_m1);
    cudaGetSymbolAddress((void**)&m2_p,    g_m2);
    cudaGetSymbolAddress((void**)&agg1_hi, g_agg1_hi);
    cudaGetSymbolAddress((void**)&agg1_lo, g_agg1_lo);
    cudaGetSymbolAddress((void**)&g1_hi,   g_g1_hi);
    cudaGetSymbolAddress((void**)&g1_lo,   g_g1_lo);
    cudaGetSymbolAddress((void**)&gn2_hi,  g_gn2_hi);
    cudaGetSymbolAddress((void**)&gn2_lo,  g_gn2_lo);
    cudaGetSymbolAddress((void**)&m1_hi,   g_m1_hi);
    cudaGetSymbolAddress((void**)&m1_lo,   g_m1_lo);
    cudaGetSymbolAddress((void**)&m2_hi,   g_m2_hi);
    cudaGetSymbolAddress((void**)&m2_lo,   g_m2_lo);
    cudaGetSymbolAddress((void**)&w1_hi,   g_W1T_hi);
    cudaGetSymbolAddress((void**)&w1_lo,   g_W1T_lo);
    cudaGetSymbolAddress((void**)&w2_hi,   g_W2T_hi);
    cudaGetSymbolAddress((void**)&w2_lo,   g_W2T_lo);
    cudaGetSymbolAddress((void**)&win_hi,  g_WinT_hi);
    cudaGetSymbolAddress((void**)&win_lo,  g_WinT_lo);
    cudaGetSymbolAddress((void**)&wh_hi,   g_WhT_hi);
    cudaGetSymbolAddress((void**)&wh_lo,   g_WhT_lo);
    cudaGetSymbolAddress((void**)&wc_hi,   g_WcT_hi);
    cudaGetSymbolAddress((void**)&wc_lo,   g_WcT_lo);

    cudaFuncSetAttribute(bf16x3_gemm_kernel,
                         cudaFuncAttributeMaxDynamicSharedMemorySize, GEMM_SMEM);
    cudaFuncSetAttribute(gemm1_gn_kernel,
                         cudaFuncAttributeMaxDynamicSharedMemorySize, GEMM_SMEM);

    const int nb = N / 256;

    // --- CSR build ---
    zero_hist_kernel<<<(N + 255) / 256, 256>>>(hs_p, hd_p, N);
    hist_kernel<<<(E + 255) / 256, 256>>>(src, dst, E, hs_p, hd_p);
    scanA_kernel<<<nb, 256>>>(hd_p, part_p, bsum_p, N);
    scanB_kernel<<<1, 1024>>>(bsum_p, nb);
    scanC_kernel<<<(N + 255) / 256, 256>>>(part_p, bsum_p, off_p, cur_p,
                                           hs_p, hd_p, rs_out_p, rs_in_p, N, E);
    fill_kernel<<<(E + 255) / 256, 256>>>(dst, src, ew, rs_out_p, E, cur_p, edge_p);

    // --- conv1 gather -> bf16 planes ---
    gather1_kernel<<<(N + 7) / 8, 256>>>(x, edge_p, off_p, agg1_hi, agg1_lo, N);

    // --- weight transposes ---
    {
        dim3 b(32, 8);
        transpose_split_kernel<<<dim3(C1 / 32, F_IN / 32), b>>>(W1, w1_hi, w1_lo, F_IN, C1);
        transpose_split_kernel<<<dim3(C2 / 32, C1 / 32), b>>>(W2, w2_hi, w2_lo, C1, C2);
        transpose_split_kernel<<<dim3(HID / 32, IN_MLP / 32), b>>>(Win, win_hi, win_lo, IN_MLP, HID);
        transpose_split_kernel<<<dim3(HID4 / 32, HID / 32), b>>>(Whid, wh_hi, wh_lo, HID, HID4);
        transpose_split_kernel<<<dim3(OUTF / 32, HID4 / 32), b>>>(Wcls, wc_hi, wc_lo, HID4, OUTF);
    }

    // --- GEMM1 with fused rs_in/leaky/graphnorm1 -> g1 planes ---
    {
        dim3 grid(1, N / GBM);
        gemm1_gn_kernel<<<grid, 256, GEMM_SMEM>>>(agg1_hi, agg1_lo, w1_hi, w1_lo,
                                                  rs_in_p, a1, gm1, bt1,
                                                  g1_hi, g1_lo);
    }

    // --- GEMM2 -> h2 fp32, then fused gather2+graphnorm2 -> gn2 planes ---
    launch_gemm(N, C1, C2, g1_hi, g1_lo, w2_hi, w2_lo, h2_p, nullptr, 0);
    gather2_gn_kernel<<<BATCH, 256>>>(h2_p, edge_p, off_p, rs_in_p,
                                      a2, gm2, bt2, gn2_hi, gn2_lo);

    // --- MLP1 + instnorm ---
    launch_gemm(BATCH, IN_MLP, HID, gn2_hi, gn2_lo, win_hi, win_lo, m1_p, nullptr, 1);
    instnorm_kernel<<<BATCH, 256>>>(m1_p, HID, m1_hi, m1_lo);

    // --- MLP2 + instnorm ---
    launch_gemm(BATCH, HID, HID4, m1_hi, m1_lo, wh_hi, wh_lo, m2_p, nullptr, 1);
    instnorm_kernel<<<BATCH, 256>>>(m2_p, HID4, m2_hi, m2_lo);

    // --- MLP3 (bf16x3) -> out ---
    launch_gemm(BATCH, HID4, OUTF, m2_hi, m2_lo, wc_hi, wc_lo, out, nullptr, 0);
}